// round 13
// baseline (speedup 1.0000x reference)
// multigrancnn GB300 — R11: register-resident radix selects (occupancy fix) +
// conv N-tile 128 with direct transposed epilogue stores.
#include <cuda_runtime.h>
#include <cuda_fp16.h>
#include <cstdint>
#include <math.h>
#include <float.h>

#define BT 256
typedef __half fp16;

// ---------------- static scratch ----------------
__device__ __align__(16) float g_qc1  [16*246*300];   // [16][300][246]
__device__ __align__(16) float g_qc2  [16*167*300];
__device__ __align__(16) float g_qc3  [16*87*300];
__device__ __align__(16) float g_qg   [16*480*300];
__device__ __align__(16) float g_dc1  [80u*486*300];
__device__ __align__(16) float g_dc2  [80u*327*300];
__device__ __align__(16) float g_dc3  [80u*167*300];
__device__ __align__(16) float g_dg   [80u*960*300];
__device__ __align__(16) float g_x0   [80*40*40];
__device__ __align__(16) float g_x1   [80*40*40];
__device__ __align__(16) fp16 g_qtb [16*480*320];
__device__ __align__(16) fp16 g_dgb [80u*960*320];
__device__ __align__(16) fp16 g_qP1[16u*256*2048];
__device__ __align__(16) fp16 g_qP2[16u*256*640];
__device__ __align__(16) fp16 g_qP3[16u*128*640];
__device__ __align__(16) fp16 g_dP1[80u*512*2048];
__device__ __align__(16) fp16 g_dP2[80u*384*640];
__device__ __align__(16) fp16 g_dP3[80u*256*640];
// weight planes padded to 384 rows (zero-init) for N-tile 128
__device__ __align__(16) fp16 g_wq1[384*2048];
__device__ __align__(16) fp16 g_wq2[384*640];
__device__ __align__(16) fp16 g_wq3[384*640];
__device__ __align__(16) fp16 g_wd1[384*2048];
__device__ __align__(16) fp16 g_wd2[384*640];
__device__ __align__(16) fp16 g_wd3[384*640];

// ---------------- helpers ----------------
__device__ __forceinline__ unsigned f2u(float f){
    unsigned u = __float_as_uint(f);
    return (u & 0x80000000u) ? ~u : (u | 0x80000000u);
}
__device__ __forceinline__ float u2f(unsigned u){
    unsigned b = (u & 0x80000000u) ? (u ^ 0x80000000u) : ~u;
    return __uint_as_float(b);
}
__device__ __forceinline__ float sigm(float x){ return 1.f/(1.f + expf(-x)); }

__device__ __forceinline__ unsigned long long pk2(float lo, float hi){
    unsigned long long r;
    asm("mov.b64 %0, {%1, %2};" : "=l"(r) : "f"(lo), "f"(hi));
    return r;
}
__device__ __forceinline__ float2 upk2(unsigned long long v){
    float2 r; asm("mov.b64 {%0, %1}, %2;" : "=f"(r.x), "=f"(r.y) : "l"(v));
    return r;
}
__device__ __forceinline__ void fma2(unsigned long long& d, unsigned long long a, unsigned long long b){
    asm("fma.rn.f32x2 %0, %1, %2, %0;" : "+l"(d) : "l"(a), "l"(b));
}

// ---------------- mma.sync primitives ----------------
__device__ __forceinline__ uint32_t smem_u32(const void* p){
    uint32_t a;
    asm("{ .reg .u64 t; cvta.to.shared.u64 t, %1; cvt.u32.u64 %0, t; }" : "=r"(a) : "l"(p));
    return a;
}
__device__ __forceinline__ void ldmx4(uint32_t* r, uint32_t addr){
    asm volatile("ldmatrix.sync.aligned.m8n8.x4.shared.b16 {%0,%1,%2,%3}, [%4];"
                 : "=r"(r[0]), "=r"(r[1]), "=r"(r[2]), "=r"(r[3]) : "r"(addr));
}
__device__ __forceinline__ void ldmx2(uint32_t* r, uint32_t addr){
    asm volatile("ldmatrix.sync.aligned.m8n8.x2.shared.b16 {%0,%1}, [%2];"
                 : "=r"(r[0]), "=r"(r[1]) : "r"(addr));
}
__device__ __forceinline__ void mma_f16(float* c, const uint32_t* a, const uint32_t* b){
    asm volatile(
        "mma.sync.aligned.m16n8k16.row.col.f32.f16.f16.f32 "
        "{%0,%1,%2,%3}, {%4,%5,%6,%7}, {%8,%9}, {%0,%1,%2,%3};"
        : "+f"(c[0]), "+f"(c[1]), "+f"(c[2]), "+f"(c[3])
        : "r"(a[0]), "r"(a[1]), "r"(a[2]), "r"(a[3]), "r"(b[0]), "r"(b[1]));
}

__device__ __forceinline__ uint4 h_pack(const float* v){
    uint4 u;
    __half2 p0 = __floats2half2_rn(v[0], v[1]);
    __half2 p1 = __floats2half2_rn(v[2], v[3]);
    __half2 p2 = __floats2half2_rn(v[4], v[5]);
    __half2 p3 = __floats2half2_rn(v[6], v[7]);
    u.x = *(unsigned*)&p0; u.y = *(unsigned*)&p1;
    u.z = *(unsigned*)&p2; u.w = *(unsigned*)&p3;
    return u;
}

// ---------------- warp-level radix select (register-resident keys) ----------
__device__ __forceinline__ int warp_excl_scan(int v, int lane){
    int x = v;
    #pragma unroll
    for (int off=1; off<32; off<<=1){
        int t = __shfl_up_sync(0xffffffffu, x, off);
        if (lane >= off) x += t;
    }
    return x - v;
}

// key[NK] per-lane registers, nv valid (indices lane-blocked by global order).
template<int NK>
__device__ __forceinline__ void warp_threshold_reg(
        const unsigned (&key)[NK], int nv, int k, int* hist, int lane,
        unsigned& T_out, int& meq_out){
    unsigned prefix = 0;
    int kr = k;
    #pragma unroll
    for (int pass=0; pass<4; pass++){
        int shift = 24 - 8*pass;
        #pragma unroll
        for (int b=lane; b<256; b+=32) hist[b] = 0;
        __syncwarp();
        if (pass==0){
            #pragma unroll
            for (int j=0;j<NK;j++)
                if (j < nv) atomicAdd(&hist[key[j]>>24], 1);
        } else {
            int hs = shift + 8;
            #pragma unroll
            for (int j=0;j<NK;j++)
                if (j < nv && (key[j]>>hs) == prefix)
                    atomicAdd(&hist[(key[j]>>shift)&255u], 1);
        }
        __syncwarp();
        int base = lane*8;
        int h[8]; int tot = 0;
        #pragma unroll
        for (int j=0;j<8;j++){ h[j] = hist[base+j]; tot += h[j]; }
        int run = tot;
        #pragma unroll
        for (int off=1; off<32; off<<=1){
            int t = __shfl_down_sync(0xffffffffu, run, off);
            if (lane + off < 32) run += t;
        }
        int acc = run - tot;
        int cum[8];
        #pragma unroll
        for (int j=7;j>=0;j--){ acc += h[j]; cum[j] = acc; }
        int d_local = -1, cumn_local = 0;
        #pragma unroll
        for (int j=0;j<8;j++){
            if (cum[j] >= kr && cum[j]-h[j] < kr){ d_local = base+j; cumn_local = cum[j]-h[j]; }
        }
        unsigned ball = __ballot_sync(0xffffffffu, d_local >= 0);
        int src = __ffs(ball) - 1;
        int d    = __shfl_sync(0xffffffffu, d_local,    src);
        int cumn = __shfl_sync(0xffffffffu, cumn_local, src);
        kr -= cumn;
        prefix = (prefix<<8) | (unsigned)d;
        __syncwarp();
    }
    T_out = prefix;
    meq_out = kr;
}

template<int NK>
__device__ __forceinline__ void warp_compact_bases_reg(
        const unsigned (&key)[NK], int nv, unsigned T, int m_eq, int lane,
        int& eq_base, int& out_base){
    int ceq = 0;
    #pragma unroll
    for (int j=0;j<NK;j++) if (j<nv) ceq += (key[j] == T);
    eq_base = warp_excl_scan(ceq, lane);
    int csel = 0;
    { int eqr = eq_base;
      #pragma unroll
      for (int j=0;j<NK;j++){
          if (j<nv){
              unsigned v = key[j]; int e = (v == T);
              csel += (v > T) || (e && eqr < m_eq);
              eqr += e;
          }
      } }
    out_base = warp_excl_scan(csel, lane);
}

// ---------------- prep kernels ----------------
__global__ void __launch_bounds__(256) prep_rows_kernel(
        const float* __restrict__ src, int srcRowsPerItem, int rowOff, int Lsrc, int Cin,
        fp16* __restrict__ Ph, int RowsAlloc, int K2p, int gran, int Lout){
    int n = blockIdx.y;
    int idx = blockIdx.x*256 + threadIdx.x;
    if (idx >= Lout*gran) return;
    int r = idx / gran, g = idx - r*gran;
    int j0 = g*8, c0 = j0 >> 1;
    int s0 = r - 4, s1 = r - 3;
    float4 fa = {0,0,0,0}, fb = {0,0,0,0};
    if (s0 >= 0 && s0 < Lsrc) fa = *(const float4*)&src[((size_t)n*srcRowsPerItem + rowOff + s0)*Cin + c0];
    if (s1 >= 0 && s1 < Lsrc) fb = *(const float4*)&src[((size_t)n*srcRowsPerItem + rowOff + s1)*Cin + c0];
    float v[8] = {fa.x,fb.x,fa.y,fb.y,fa.z,fb.z,fa.w,fb.w};
    *(uint4*)(Ph + ((size_t)n*RowsAlloc + r)*K2p + j0) = h_pack(v);
}

__global__ void __launch_bounds__(256) prep_docs_kernel(
        const float* __restrict__ pos, const float* __restrict__ neg,
        fp16* __restrict__ Ph){
    const int Lsrc = 479, Cin = 1024, gran = 256, RowsAlloc = 512, K2p = 2048, Lout = 486;
    int n = blockIdx.y;
    int s = n >> 4, b = n & 15;
    const float* src = (s==0) ? (pos + (size_t)b*Lsrc*Cin)
                              : (neg + ((size_t)(s-1)*16 + b)*Lsrc*Cin);
    int idx = blockIdx.x*256 + threadIdx.x;
    if (idx >= Lout*gran) return;
    int r = idx / gran, g = idx - r*gran;
    int j0 = g*8, c0 = j0 >> 1;
    int s0 = r - 4, s1 = r - 3;
    float4 fa = {0,0,0,0}, fb = {0,0,0,0};
    if (s0 >= 0 && s0 < Lsrc) fa = *(const float4*)&src[(size_t)s0*Cin + c0];
    if (s1 >= 0 && s1 < Lsrc) fb = *(const float4*)&src[(size_t)s1*Cin + c0];
    float v[8] = {fa.x,fb.x,fa.y,fb.y,fa.z,fb.z,fa.w,fb.w};
    *(uint4*)(Ph + ((size_t)n*RowsAlloc + r)*K2p + j0) = h_pack(v);
}

__global__ void __launch_bounds__(256) wprep_kernel(
        const float* __restrict__ w, fp16* __restrict__ Wh, int K2, int K2p){
    int gran = K2 >> 3;
    int idx = blockIdx.x*256 + threadIdx.x;
    if (idx >= 300*gran) return;
    int o = idx / gran, g = idx - o*gran;
    int j0 = g*8;
    const float* wr = w + (size_t)o*K2 + j0;
    float4 fa = *(const float4*)wr;
    float4 fb = *(const float4*)(wr+4);
    float v[8] = {fa.x,fa.y,fa.z,fa.w,fb.x,fb.y,fb.z,fb.w};
    *(uint4*)(Wh + (size_t)o*K2p + j0) = h_pack(v);
}

// ---------------- conv1d via mma.sync fp16, 128L x 128O tile ----------------
#define CPAD 72
#define OFF_A 0
#define OFF_B (128*CPAD*2)
#define CONV_SMEM_SZ (2*128*CPAD*2)   // 36864

__global__ void __launch_bounds__(256) conv1d_mma_kernel(
        const fp16* __restrict__ Ph, const fp16* __restrict__ Wh,
        const float* __restrict__ bias, float* __restrict__ outT,
        int RowsAlloc, int K2p, int nch, int Lout){
    extern __shared__ __align__(16) char smem[];
    uint32_t sb = smem_u32(smem);
    int tid = threadIdx.x, wid = tid>>5, lane = tid&31;
    int wm = wid & 3, wn = wid >> 2;            // 4(m) x 2(n); warp 32L x 64O
    int l0 = blockIdx.x*128, n0 = blockIdx.y*128, nb = blockIdx.z;
    const fp16* PhN = Ph + (size_t)nb*RowsAlloc*K2p;

    float acc[2][8][4];
    #pragma unroll
    for (int mt=0; mt<2; mt++)
        #pragma unroll
        for (int nt=0; nt<8; nt++)
            #pragma unroll
            for (int e=0; e<4; e++) acc[mt][nt][e] = 0.f;

    int a_row_add = (lane & 7) + ((lane >> 3) & 1)*8;
    int a_col_add = ((lane >> 4) & 1)*8;
    int b_row_add = (lane & 7);
    int b_col_add = ((lane >> 3) & 1)*8;

    for (int ch=0; ch<nch; ch++){
        int jc = ch*64;
        #pragma unroll
        for (int it=0; it<4; it++){
            int task = tid + it*256;
            int r = task >> 3, g = task & 7;
            size_t go = (size_t)(l0 + r)*K2p + jc + g*8;
            *(uint4*)(smem + OFF_A + (uint32_t)(r*CPAD + g*8)*2) = *(const uint4*)(PhN + go);
        }
        #pragma unroll
        for (int it=0; it<4; it++){
            int task = tid + it*256;
            int r = task >> 3, g = task & 7;
            size_t go = (size_t)(n0 + r)*K2p + jc + g*8;
            *(uint4*)(smem + OFF_B + (uint32_t)(r*CPAD + g*8)*2) = *(const uint4*)(Wh + go);
        }
        __syncthreads();
        #pragma unroll
        for (int ks=0; ks<4; ks++){
            uint32_t a_[2][4], b_[8][2];
            #pragma unroll
            for (int mt=0; mt<2; mt++){
                int row = wm*32 + mt*16 + a_row_add;
                ldmx4(a_[mt], sb + OFF_A + (uint32_t)(row*CPAD + ks*16 + a_col_add)*2);
            }
            #pragma unroll
            for (int nt=0; nt<8; nt++){
                int row = wn*64 + nt*8 + b_row_add;
                ldmx2(b_[nt], sb + OFF_B + (uint32_t)(row*CPAD + ks*16 + b_col_add)*2);
            }
            #pragma unroll
            for (int mt=0; mt<2; mt++)
                #pragma unroll
                for (int nt=0; nt<8; nt++)
                    mma_f16(acc[mt][nt], a_[mt], b_[nt]);
        }
        __syncthreads();
    }

    // direct transposed epilogue: outT[n][o][l]
    int gid = lane >> 2, tig = lane & 3;
    float* outN = outT + (size_t)nb*300*Lout;
    #pragma unroll
    for (int mt=0; mt<2; mt++){
        int r0 = l0 + wm*32 + mt*16 + gid;
        int r1 = r0 + 8;
        bool v0 = (r0 < Lout), v1 = (r1 < Lout);
        #pragma unroll
        for (int nt=0; nt<8; nt++){
            int c = n0 + wn*64 + nt*8 + tig*2;
            if (c < 300){
                float b0 = __ldg(&bias[c]);
                if (v0) outN[(size_t)c*Lout + r0] = tanhf(acc[mt][nt][0] + b0);
                if (v1) outN[(size_t)c*Lout + r1] = tanhf(acc[mt][nt][2] + b0);
            }
            if (c+1 < 300){
                float b1 = __ldg(&bias[c+1]);
                if (v0) outN[(size_t)(c+1)*Lout + r0] = tanhf(acc[mt][nt][1] + b1);
                if (v1) outN[(size_t)(c+1)*Lout + r1] = tanhf(acc[mt][nt][3] + b1);
            }
        }
    }
}

// ---------------- channel kmax (1024 -> 300): warp per task, reg keys -------
__global__ void __launch_bounds__(256) kmax_ch_q_kernel(
        const float* __restrict__ query, float* __restrict__ qg){
    __shared__ int hist[8][256];
    int wid = threadIdx.x >> 5, lane = threadIdx.x & 31;
    int l = blockIdx.x*8 + wid, n = blockIdx.y;
    if (l >= 239) return;
    const float4* r4 = (const float4*)(query + ((size_t)n*239 + l)*1024 + lane*32);
    unsigned key[32];
    #pragma unroll
    for (int q=0;q<8;q++){
        float4 f = r4[q];
        key[q*4+0]=f2u(f.x); key[q*4+1]=f2u(f.y);
        key[q*4+2]=f2u(f.z); key[q*4+3]=f2u(f.w);
    }
    unsigned T; int m_eq;
    warp_threshold_reg<32>(key, 32, 300, hist[wid], lane, T, m_eq);
    int eq_base, out_base;
    warp_compact_bases_reg<32>(key, 32, T, m_eq, lane, eq_base, out_base);
    float* orow = qg + (size_t)n*480*300 + (size_t)l*300;
    { int eqr = eq_base, p = out_base;
      #pragma unroll
      for (int j=0;j<32;j++){
          unsigned v = key[j]; int e = (v == T);
          if ((v > T) || (e && eqr < m_eq)) orow[p++] = u2f(v);
          eqr += e;
      } }
}

__global__ void __launch_bounds__(256) kmax_ch_d_kernel(
        const float* __restrict__ pos, const float* __restrict__ neg,
        float* __restrict__ dg, fp16* __restrict__ dgh){
    __shared__ int hist[8][256];
    int wid = threadIdx.x >> 5, lane = threadIdx.x & 31;
    int l = blockIdx.x*8 + wid, n = blockIdx.y;
    if (l >= 479) return;
    int s = n >> 4, b = n & 15;
    const float* row = (s==0) ? (pos + ((size_t)b*479 + l)*1024)
                              : (neg + (((size_t)(s-1)*16 + b)*479 + l)*1024);
    const float4* r4 = (const float4*)(row + lane*32);
    unsigned key[32];
    #pragma unroll
    for (int q=0;q<8;q++){
        float4 f = r4[q];
        key[q*4+0]=f2u(f.x); key[q*4+1]=f2u(f.y);
        key[q*4+2]=f2u(f.z); key[q*4+3]=f2u(f.w);
    }
    unsigned T; int m_eq;
    warp_threshold_reg<32>(key, 32, 300, hist[wid], lane, T, m_eq);
    int eq_base, out_base;
    warp_compact_bases_reg<32>(key, 32, T, m_eq, lane, eq_base, out_base);
    float* orow = dg + (size_t)n*960*300 + (size_t)l*300;
    fp16* prow = dgh + ((size_t)n*960 + l)*320;
    { int eqr = eq_base, p = out_base;
      #pragma unroll
      for (int j=0;j<32;j++){
          unsigned v = key[j]; int e = (v == T);
          if ((v > T) || (e && eqr < m_eq)){
              float f = u2f(v);
              orow[p] = f;
              prow[p] = __float2half_rn(f);
              p++;
          }
          eqr += e;
      } }
}

// ---------------- length kmax (transposed input), reg keys ------------------
#define LIPT 16
__global__ void __launch_bounds__(256) kmax_len_q_kernel(
        const float* __restrict__ srcT, int Lin, int k,
        float* __restrict__ dstBase){
    __shared__ int hist[8][256];
    int wid = threadIdx.x >> 5, lane = threadIdx.x & 31;
    int o = blockIdx.x*8 + wid, n = blockIdx.y;
    if (o >= 300) return;
    const float* row = srcT + ((size_t)n*300 + o)*Lin;
    int ipt = (Lin + 31)/32;
    int beg = lane*ipt;
    int nv = Lin - beg; if (nv < 0) nv = 0; if (nv > ipt) nv = ipt;
    unsigned key[LIPT];
    #pragma unroll
    for (int j=0;j<LIPT;j++)
        key[j] = (j < nv) ? f2u(row[beg + j]) : 0u;
    unsigned T; int m_eq;
    warp_threshold_reg<LIPT>(key, nv, k, hist[wid], lane, T, m_eq);
    int eq_base, out_base;
    warp_compact_bases_reg<LIPT>(key, nv, T, m_eq, lane, eq_base, out_base);
    float* dn = dstBase + (size_t)n*480*300;
    { int eqr = eq_base, p = out_base;
      #pragma unroll
      for (int j=0;j<LIPT;j++){
          if (j < nv){
              unsigned v = key[j]; int e = (v == T);
              if ((v > T) || (e && eqr < m_eq)) dn[(size_t)(p++)*300 + o] = u2f(v);
              eqr += e;
          }
      } }
}

__global__ void __launch_bounds__(256) kmax_len_d_kernel(
        const float* __restrict__ srcT, int Lin, int k, int rowOff,
        float* __restrict__ dg, fp16* __restrict__ dgh){
    __shared__ int hist[8][256];
    int wid = threadIdx.x >> 5, lane = threadIdx.x & 31;
    int o = blockIdx.x*8 + wid, n = blockIdx.y;
    if (o >= 300) return;
    const float* row = srcT + ((size_t)n*300 + o)*Lin;
    int ipt = (Lin + 31)/32;
    int beg = lane*ipt;
    int nv = Lin - beg; if (nv < 0) nv = 0; if (nv > ipt) nv = ipt;
    unsigned key[LIPT];
    #pragma unroll
    for (int j=0;j<LIPT;j++)
        key[j] = (j < nv) ? f2u(row[beg + j]) : 0u;
    unsigned T; int m_eq;
    warp_threshold_reg<LIPT>(key, nv, k, hist[wid], lane, T, m_eq);
    int eq_base, out_base;
    warp_compact_bases_reg<LIPT>(key, nv, T, m_eq, lane, eq_base, out_base);
    { int eqr = eq_base, p = out_base;
      #pragma unroll
      for (int j=0;j<LIPT;j++){
          if (j < nv){
              unsigned v = key[j]; int e = (v == T);
              if ((v > T) || (e && eqr < m_eq)){
                  float f = u2f(v);
                  size_t r = (size_t)n*960 + rowOff + p;
                  dg[r*300 + o]  = f;
                  dgh[r*320 + o] = __float2half_rn(f);
                  p++;
              }
              eqr += e;
          }
      } }
}

// ---------------- k=1 max over length ----------------
__global__ void __launch_bounds__(256) maxlen_q_kernel(
        const float* __restrict__ srcT, int Lin, float* __restrict__ dstBase){
    int w = threadIdx.x >> 5, lane = threadIdx.x & 31;
    int o = blockIdx.x*8 + w;
    int n = blockIdx.y;
    if (o >= 300) return;
    const float* row = srcT + ((size_t)n*300 + o)*Lin;
    float m = -FLT_MAX;
    for (int l=lane; l<Lin; l+=32) m = fmaxf(m, row[l]);
    #pragma unroll
    for (int off=16; off; off>>=1)
        m = fmaxf(m, __shfl_down_sync(0xffffffffu, m, off));
    if (lane == 0) dstBase[(size_t)n*480*300 + o] = m;
}

__global__ void __launch_bounds__(256) maxlen_d_kernel(
        const float* __restrict__ srcT, int Lin,
        float* __restrict__ dg, fp16* __restrict__ dgh){
    int w = threadIdx.x >> 5, lane = threadIdx.x & 31;
    int o = blockIdx.x*8 + w;
    int n = blockIdx.y;
    if (o >= 300) return;
    const float* row = srcT + ((size_t)n*300 + o)*Lin;
    float m = -FLT_MAX;
    for (int l=lane; l<Lin; l+=32) m = fmaxf(m, row[l]);
    #pragma unroll
    for (int off=16; off; off>>=1)
        m = fmaxf(m, __shfl_down_sync(0xffffffffu, m, off));
    if (lane == 0){
        size_t r = (size_t)n*960 + 959;
        dg[r*300 + o] = m;
        dgh[r*320 + o] = __float2half_rn(m);
    }
}

// ---------------- SGEMM qt = qg @ bw, fp16 out (pitch 320) ------------------
__global__ void __launch_bounds__(256) sgemm_qt_kernel(
        const float* __restrict__ A, const float* __restrict__ B,
        fp16* __restrict__ qth, int M, int K){
    __shared__ float sA[16][68];
    __shared__ float sB[16][68];
    int tid = threadIdx.x;
    int tx = tid & 15, ty = tid >> 4;
    int n0 = blockIdx.x * 64, m0 = blockIdx.y * 64;
    unsigned long long acc2[4][2];
    #pragma unroll
    for (int i=0;i<4;i++){ acc2[i][0]=0ull; acc2[i][1]=0ull; }
    int row = ty*4, col = tx*4;
    for (int k0 = 0; k0 < K; k0 += 16){
        for (int idx = tid; idx < 1024; idx += BT){
            int kk = idx & 15, m = idx >> 4;
            int gm = m0 + m, gk = k0 + kk;
            sA[kk][m] = (gm < M && gk < K) ? A[(size_t)gm*K + gk] : 0.f;
        }
        for (int idx = tid; idx < 1024; idx += BT){
            int nn = idx & 63, kk = idx >> 6;
            int gn = n0 + nn, gk = k0 + kk;
            sB[kk][nn] = (gn < 300 && gk < K) ? B[(size_t)gk*300 + gn] : 0.f;
        }
        __syncthreads();
        #pragma unroll
        for (int kk=0; kk<16; kk++){
            float4 a4 = *(const float4*)&sA[kk][row];
            ulonglong2 b2 = *(const ulonglong2*)&sB[kk][col];
            unsigned long long d0 = pk2(a4.x,a4.x);
            unsigned long long d1 = pk2(a4.y,a4.y);
            unsigned long long d2 = pk2(a4.z,a4.z);
            unsigned long long d3 = pk2(a4.w,a4.w);
            fma2(acc2[0][0], d0, b2.x); fma2(acc2[0][1], d0, b2.y);
            fma2(acc2[1][0], d1, b2.x); fma2(acc2[1][1], d1, b2.y);
            fma2(acc2[2][0], d2, b2.x); fma2(acc2[2][1], d2, b2.y);
            fma2(acc2[3][0], d3, b2.x); fma2(acc2[3][1], d3, b2.y);
        }
        __syncthreads();
    }
    #pragma unroll
    for (int i=0;i<4;i++){
        int gm = m0 + row + i;
        if (gm >= M) continue;
        #pragma unroll
        for (int j2=0;j2<2;j2++){
            float2 v = upk2(acc2[i][j2]);
            int gn = n0 + col + 2*j2;
            float x0 = (gn   < 300) ? v.x : 0.f;
            float x1 = (gn+1 < 300) ? v.y : 0.f;
            size_t off = (size_t)gm*320 + gn;
            qth[off]   = __float2half_rn(x0);
            qth[off+1] = __float2half_rn(x1);
        }
    }
}

// ---------------- fused match GEMM (mma fp16) + pool + sigmoid --------------
__global__ void __launch_bounds__(256) mpool_mma_kernel(
        const fp16* __restrict__ qth, const fp16* __restrict__ dgh,
        const float* __restrict__ bbp, float* __restrict__ xout){
    __shared__ __align__(16) fp16 sQ[96*40];
    __shared__ __align__(16) fp16 sD[96*40];
    __shared__ unsigned pool[32];
    int tid = threadIdx.x, wid = tid>>5, lane = tid&31;
    int wm = wid & 1, wn = wid >> 1;
    int n = blockIdx.z, b = n & 15;
    int q0 = blockIdx.y*96, d0 = blockIdx.x*96;
    const fp16* Q = qth + ((size_t)b*480 + q0)*320;
    const fp16* D = dgh + ((size_t)n*960 + d0)*320;

    float acc[3][3][4];
    #pragma unroll
    for (int mt=0; mt<3; mt++)
        #pragma unroll
        for (int nt=0; nt<3; nt++)
            #pragma unroll
            for (int e=0; e<4; e++) acc[mt][nt][e] = 0.f;

    int a_row_add = (lane & 7) + ((lane >> 3) & 1)*8;
    int a_col_add = ((lane >> 4) & 1)*8;
    int b_row_add = (lane & 7);
    int b_col_add = ((lane >> 3) & 1)*8;
    uint32_t sQ_b = smem_u32(sQ), sD_b = smem_u32(sD);

    for (int ch=0; ch<10; ch++){
        int k0 = ch*32;
        #pragma unroll
        for (int it=0; it<3; it++){
            int t = tid + it*256;
            int plane = t / 384, rem = t - plane*384;
            int r = rem >> 2, g = rem & 3;
            const fp16* gsrc = plane ? D : Q;
            fp16* sdst = plane ? sD : sQ;
            uint4 v = *(const uint4*)(gsrc + (size_t)r*320 + k0 + g*8);
            *(uint4*)(sdst + r*40 + g*8) = v;
        }
        __syncthreads();
        #pragma unroll
        for (int ks=0; ks<2; ks++){
            uint32_t q_[3][4], d_[3][2];
            #pragma unroll
            for (int mt=0; mt<3; mt++){
                int row = wm*48 + mt*16 + a_row_add;
                ldmx4(q_[mt], sQ_b + (uint32_t)(row*40 + ks*16 + a_col_add)*2);
            }
            #pragma unroll
            for (int nt=0; nt<3; nt++){
                int row = wn*24 + nt*8 + b_row_add;
                ldmx2(d_[nt], sD_b + (uint32_t)(row*40 + ks*16 + b_col_add)*2);
            }
            #pragma unroll
            for (int mt=0; mt<3; mt++)
                #pragma unroll
                for (int nt=0; nt<3; nt++)
                    mma_f16(acc[mt][nt], q_[mt], d_[nt]);
        }
        __syncthreads();
    }

    if (tid < 32) pool[tid] = 0u;
    __syncthreads();
    int gid = lane >> 2;
    #pragma unroll
    for (int mt=0; mt<3; mt++){
        float m0 = -FLT_MAX, m1 = -FLT_MAX;
        #pragma unroll
        for (int nt=0; nt<3; nt++){
            m0 = fmaxf(m0, fmaxf(acc[mt][nt][0], acc[mt][nt][1]));
            m1 = fmaxf(m1, fmaxf(acc[mt][nt][2], acc[mt][nt][3]));
        }
        int r0 = wm*48 + mt*16 + gid;
        int r1 = r0 + 8;
        atomicMax(&pool[(r0/12)*4 + wn], f2u(m0));
        atomicMax(&pool[(r1/12)*4 + wn], f2u(m1));
    }
    __syncthreads();
    if (tid < 32){
        int qc = tid >> 2, dc = tid & 3;
        float logit = u2f(pool[tid]) + bbp[0];
        int gi = blockIdx.y*8 + qc, gj = blockIdx.x*4 + dc;
        xout[((size_t)n*40 + gi)*40 + gj] = sigm(logit);
    }
}

// ---------------- 2D conv tower block ----------------
__global__ void __launch_bounds__(256) convtower_kernel(
        const float* __restrict__ xin, const float* __restrict__ mw,
        const float* __restrict__ mb, float* __restrict__ xout){
    __shared__ float sx[40][40];
    __shared__ float swt[50][4];
    __shared__ float sb[50];
    int n = blockIdx.x, tid = threadIdx.x;
    for (int idx=tid; idx<1600; idx+=blockDim.x)
        sx[idx/40][idx%40] = xin[(size_t)n*1600 + idx];
    for (int idx=tid; idx<200; idx+=blockDim.x)
        swt[idx>>2][idx&3] = mw[idx];
    for (int idx=tid; idx<50; idx+=blockDim.x)
        sb[idx] = mb[idx];
    __syncthreads();
    for (int cell=tid; cell<1600; cell+=blockDim.x){
        int i = cell/40, j = cell%40;
        int hs = (i*47)/40,  he = ((i+1)*47 + 39)/40;
        int ws = (j*47)/40,  we = ((j+1)*47 + 39)/40;
        float m = -FLT_MAX;
        for (int h=hs; h<he; h++)
            for (int w=ws; w<we; w++){
                int r0=h-4, r1=h-3, c0=w-4, c1=w-3;
                float x00 = (r0>=0 && r0<40 && c0>=0 && c0<40) ? sx[r0][c0] : 0.f;
                float x01 = (r0>=0 && r0<40 && c1>=0 && c1<40) ? sx[r0][c1] : 0.f;
                float x10 = (r1>=0 && r1<40 && c0>=0 && c0<40) ? sx[r1][c0] : 0.f;
                float x11 = (r1>=0 && r1<40 && c1>=0 && c1<40) ? sx[r1][c1] : 0.f;
                for (int o=0;o<50;o++){
                    float l = fmaf(x00, swt[o][0],
                              fmaf(x01, swt[o][1],
                              fmaf(x10, swt[o][2],
                              fmaf(x11, swt[o][3], sb[o]))));
                    m = fmaxf(m, l);
                }
            }
        xout[(size_t)n*1600 + cell] = sigm(m);
    }
}

// ---------------- final logistic head ----------------
__global__ void __launch_bounds__(64) final_kernel(
        const float* __restrict__ feat, const float* __restrict__ lw,
        const float* __restrict__ lb, float* __restrict__ out){
    __shared__ float sh[40];
    int n = blockIdx.x, tid = threadIdx.x;
    if (tid < 40){
        float a = 0.f;
        const float* f = feat + (size_t)n*1600 + tid*40;
        for (int j=0;j<40;j++) a += f[j]*lw[j];
        sh[tid] = sigm(a + lb[0]);
    }
    __syncthreads();
    if (tid == 0){
        float a = 0.f;
        for (int i=0;i<40;i++) a += sh[i]*lw[i];
        out[n] = sigm(a + lb[0]);
    }
}

// ---------------- launch ----------------
extern "C" void kernel_launch(void* const* d_in, const int* in_sizes, int n_in,
                              void* d_out, int out_size){
    const float* query = (const float*)d_in[0];
    const float* pos   = (const float*)d_in[1];
    const float* neg   = (const float*)d_in[2];
    const float* qw1 = (const float*)d_in[3];  const float* qb1 = (const float*)d_in[4];
    const float* qw2 = (const float*)d_in[5];  const float* qb2 = (const float*)d_in[6];
    const float* qw3 = (const float*)d_in[7];  const float* qb3 = (const float*)d_in[8];
    const float* dw1 = (const float*)d_in[9];  const float* db1 = (const float*)d_in[10];
    const float* dw2 = (const float*)d_in[11]; const float* db2 = (const float*)d_in[12];
    const float* dw3 = (const float*)d_in[13]; const float* db3 = (const float*)d_in[14];
    const float* bw  = (const float*)d_in[15]; const float* bb  = (const float*)d_in[16];
    const float* mw1 = (const float*)d_in[17]; const float* mb1 = (const float*)d_in[18];
    const float* mw2 = (const float*)d_in[19]; const float* mb2 = (const float*)d_in[20];
    const float* mw3 = (const float*)d_in[21]; const float* mb3 = (const float*)d_in[22];
    const float* lw  = (const float*)d_in[23]; const float* lb  = (const float*)d_in[24];
    float* out = (float*)d_out;

    float *qc1, *qc2, *qc3, *qg, *dc1, *dc2, *dc3, *dg, *x0, *x1;
    fp16 *qtb, *dgb, *qP1, *qP2, *qP3, *dP1, *dP2, *dP3;
    fp16 *wq1, *wq2, *wq3, *wd1, *wd2, *wd3;
    cudaGetSymbolAddress((void**)&qc1,  g_qc1);
    cudaGetSymbolAddress((void**)&qc2,  g_qc2);
    cudaGetSymbolAddress((void**)&qc3,  g_qc3);
    cudaGetSymbolAddress((void**)&qg,   g_qg);
    cudaGetSymbolAddress((void**)&dc1,  g_dc1);
    cudaGetSymbolAddress((void**)&dc2,  g_dc2);
    cudaGetSymbolAddress((void**)&dc3,  g_dc3);
    cudaGetSymbolAddress((void**)&dg,   g_dg);
    cudaGetSymbolAddress((void**)&x0,   g_x0);
    cudaGetSymbolAddress((void**)&x1,   g_x1);
    cudaGetSymbolAddress((void**)&qtb,  g_qtb);
    cudaGetSymbolAddress((void**)&dgb,  g_dgb);
    cudaGetSymbolAddress((void**)&qP1,  g_qP1);
    cudaGetSymbolAddress((void**)&qP2,  g_qP2);
    cudaGetSymbolAddress((void**)&qP3,  g_qP3);
    cudaGetSymbolAddress((void**)&dP1,  g_dP1);
    cudaGetSymbolAddress((void**)&dP2,  g_dP2);
    cudaGetSymbolAddress((void**)&dP3,  g_dP3);
    cudaGetSymbolAddress((void**)&wq1,  g_wq1);
    cudaGetSymbolAddress((void**)&wq2,  g_wq2);
    cudaGetSymbolAddress((void**)&wq3,  g_wq3);
    cudaGetSymbolAddress((void**)&wd1,  g_wd1);
    cudaGetSymbolAddress((void**)&wd2,  g_wd2);
    cudaGetSymbolAddress((void**)&wd3,  g_wd3);

    cudaFuncSetAttribute(conv1d_mma_kernel,
                         cudaFuncAttributeMaxDynamicSharedMemorySize, CONV_SMEM_SZ);

    wprep_kernel<<<300, 256>>>(dw1, wd1, 2048, 2048);
    prep_docs_kernel<<<dim3(486, 80), 256>>>(pos, neg, dP1);
    kmax_ch_q_kernel<<<dim3(30, 16), 256>>>(query, qg);
    kmax_ch_d_kernel<<<dim3(60, 80), 256>>>(pos, neg, dg, dgb);
    wprep_kernel<<<300, 256>>>(qw1, wq1, 2048, 2048);
    conv1d_mma_kernel<<<dim3(4,3,80), 256, CONV_SMEM_SZ>>>(dP1, wd1, db1, dc1, 512, 2048, 32, 486);
    kmax_len_d_kernel<<<dim3(38,80), 256>>>(dc1, 486, 320, 479, dg, dgb);

    wprep_kernel<<<88, 256>>>(qw2, wq2, 600, 640);
    wprep_kernel<<<88, 256>>>(qw3, wq3, 600, 640);
    wprep_kernel<<<88, 256>>>(dw2, wd2, 600, 640);
    wprep_kernel<<<88, 256>>>(dw3, wd3, 600, 640);

    // ===== query tower =====
    prep_rows_kernel<<<dim3(246, 16), 256>>>(query, 239, 0, 239, 1024, qP1, 256, 2048, 256, 246);
    conv1d_mma_kernel<<<dim3(2,3,16), 256, CONV_SMEM_SZ>>>(qP1, wq1, qb1, qc1, 256, 2048, 32, 246);
    kmax_len_q_kernel<<<dim3(38,16), 256>>>(qc1, 246, 160, qg + 239*300);
    prep_rows_kernel<<<dim3(49, 16), 256>>>(qg, 480, 239, 160, 300, qP2, 256, 640, 75, 167);
    conv1d_mma_kernel<<<dim3(2,3,16), 256, CONV_SMEM_SZ>>>(qP2, wq2, qb2, qc2, 256, 640, 10, 167);
    kmax_len_q_kernel<<<dim3(38,16), 256>>>(qc2, 167, 80, qg + 399*300);
    prep_rows_kernel<<<dim3(26, 16), 256>>>(qg, 480, 399, 80, 300, qP3, 128, 640, 75, 87);
    conv1d_mma_kernel<<<dim3(1,3,16), 256, CONV_SMEM_SZ>>>(qP3, wq3, qb3, qc3, 128, 640, 10, 87);
    maxlen_q_kernel<<<dim3(38,16), 256>>>(qc3, 87, qg + 479*300);

    // ===== doc tower (cont.) =====
    prep_rows_kernel<<<dim3(96, 80), 256>>>(dg, 960, 479, 320, 300, dP2, 384, 640, 75, 327);
    conv1d_mma_kernel<<<dim3(3,3,80), 256, CONV_SMEM_SZ>>>(dP2, wd2, db2, dc2, 384, 640, 10, 327);
    kmax_len_d_kernel<<<dim3(38,80), 256>>>(dc2, 327, 160, 799, dg, dgb);
    prep_rows_kernel<<<dim3(49, 80), 256>>>(dg, 960, 799, 160, 300, dP3, 256, 640, 75, 167);
    conv1d_mma_kernel<<<dim3(2,3,80), 256, CONV_SMEM_SZ>>>(dP3, wd3, db3, dc3, 256, 640, 10, 167);
    maxlen_d_kernel<<<dim3(38,80), 256>>>(dc3, 167, dg, dgb);

    // ===== bilinear + fused match/pool =====
    sgemm_qt_kernel<<<dim3(5, 120), 256>>>(qg, bw, qtb, 16*480, 300);
    mpool_mma_kernel<<<dim3(10, 5, 80), 256>>>(qtb, dgb, bb, x0);

    convtower_kernel<<<80, 256>>>(x0, mw1, mb1, x1);
    convtower_kernel<<<80, 256>>>(x1, mw2, mb2, x0);
    convtower_kernel<<<80, 256>>>(x0, mw3, mb3, x1);

    final_kernel<<<80, 64>>>(x1, lw, lb, out);
}

// round 16
// speedup vs baseline: 1.4895x; 1.4895x over previous
// multigrancnn GB300 — R12: revert R11 (reg-keys + wide conv tile both regressed);
// R10 pipeline with 4-warp kmax blocks (smem/block halved -> ~2x occupancy).
#include <cuda_runtime.h>
#include <cuda_fp16.h>
#include <cstdint>
#include <math.h>
#include <float.h>

#define BT 256
typedef __half fp16;

// ---------------- static scratch ----------------
__device__ __align__(16) float g_qc1  [16*246*300];   // [16][300][246]
__device__ __align__(16) float g_qc2  [16*167*300];
__device__ __align__(16) float g_qc3  [16*87*300];
__device__ __align__(16) float g_qg   [16*480*300];
__device__ __align__(16) float g_dc1  [80u*486*300];
__device__ __align__(16) float g_dc2  [80u*327*300];
__device__ __align__(16) float g_dc3  [80u*167*300];
__device__ __align__(16) float g_dg   [80u*960*300];
__device__ __align__(16) float g_x0   [80*40*40];
__device__ __align__(16) float g_x1   [80*40*40];
__device__ __align__(16) fp16 g_qtb [16*480*320];
__device__ __align__(16) fp16 g_dgb [80u*960*320];
__device__ __align__(16) fp16 g_qP1[16u*256*2048];
__device__ __align__(16) fp16 g_qP2[16u*256*640];
__device__ __align__(16) fp16 g_qP3[16u*128*640];
__device__ __align__(16) fp16 g_dP1[80u*512*2048];
__device__ __align__(16) fp16 g_dP2[80u*384*640];
__device__ __align__(16) fp16 g_dP3[80u*256*640];
__device__ __align__(16) fp16 g_wq1[320*2048];
__device__ __align__(16) fp16 g_wq2[320*640];
__device__ __align__(16) fp16 g_wq3[320*640];
__device__ __align__(16) fp16 g_wd1[320*2048];
__device__ __align__(16) fp16 g_wd2[320*640];
__device__ __align__(16) fp16 g_wd3[320*640];

// ---------------- helpers ----------------
__device__ __forceinline__ unsigned f2u(float f){
    unsigned u = __float_as_uint(f);
    return (u & 0x80000000u) ? ~u : (u | 0x80000000u);
}
__device__ __forceinline__ float u2f(unsigned u){
    unsigned b = (u & 0x80000000u) ? (u ^ 0x80000000u) : ~u;
    return __uint_as_float(b);
}
__device__ __forceinline__ float sigm(float x){ return 1.f/(1.f + expf(-x)); }

__device__ __forceinline__ unsigned long long pk2(float lo, float hi){
    unsigned long long r;
    asm("mov.b64 %0, {%1, %2};" : "=l"(r) : "f"(lo), "f"(hi));
    return r;
}
__device__ __forceinline__ float2 upk2(unsigned long long v){
    float2 r; asm("mov.b64 {%0, %1}, %2;" : "=f"(r.x), "=f"(r.y) : "l"(v));
    return r;
}
__device__ __forceinline__ void fma2(unsigned long long& d, unsigned long long a, unsigned long long b){
    asm("fma.rn.f32x2 %0, %1, %2, %0;" : "+l"(d) : "l"(a), "l"(b));
}

// ---------------- mma.sync primitives ----------------
__device__ __forceinline__ uint32_t smem_u32(const void* p){
    uint32_t a;
    asm("{ .reg .u64 t; cvta.to.shared.u64 t, %1; cvt.u32.u64 %0, t; }" : "=r"(a) : "l"(p));
    return a;
}
__device__ __forceinline__ void ldmx4(uint32_t* r, uint32_t addr){
    asm volatile("ldmatrix.sync.aligned.m8n8.x4.shared.b16 {%0,%1,%2,%3}, [%4];"
                 : "=r"(r[0]), "=r"(r[1]), "=r"(r[2]), "=r"(r[3]) : "r"(addr));
}
__device__ __forceinline__ void ldmx2(uint32_t* r, uint32_t addr){
    asm volatile("ldmatrix.sync.aligned.m8n8.x2.shared.b16 {%0,%1}, [%2];"
                 : "=r"(r[0]), "=r"(r[1]) : "r"(addr));
}
__device__ __forceinline__ void mma_f16(float* c, const uint32_t* a, const uint32_t* b){
    asm volatile(
        "mma.sync.aligned.m16n8k16.row.col.f32.f16.f16.f32 "
        "{%0,%1,%2,%3}, {%4,%5,%6,%7}, {%8,%9}, {%0,%1,%2,%3};"
        : "+f"(c[0]), "+f"(c[1]), "+f"(c[2]), "+f"(c[3])
        : "r"(a[0]), "r"(a[1]), "r"(a[2]), "r"(a[3]), "r"(b[0]), "r"(b[1]));
}

__device__ __forceinline__ uint4 h_pack(const float* v){
    uint4 u;
    __half2 p0 = __floats2half2_rn(v[0], v[1]);
    __half2 p1 = __floats2half2_rn(v[2], v[3]);
    __half2 p2 = __floats2half2_rn(v[4], v[5]);
    __half2 p3 = __floats2half2_rn(v[6], v[7]);
    u.x = *(unsigned*)&p0; u.y = *(unsigned*)&p1;
    u.z = *(unsigned*)&p2; u.w = *(unsigned*)&p3;
    return u;
}

// ---------------- warp-level radix select (smem keys) ----------------
__device__ __forceinline__ int warp_excl_scan(int v, int lane){
    int x = v;
    #pragma unroll
    for (int off=1; off<32; off<<=1){
        int t = __shfl_up_sync(0xffffffffu, x, off);
        if (lane >= off) x += t;
    }
    return x - v;
}

__device__ __forceinline__ void warp_threshold(
        const unsigned* skey, int n, int k, int* hist, int lane,
        unsigned& T_out, int& meq_out){
    unsigned prefix = 0;
    int kr = k;
    #pragma unroll
    for (int pass=0; pass<4; pass++){
        int shift = 24 - 8*pass;
        #pragma unroll
        for (int b=lane; b<256; b+=32) hist[b] = 0;
        __syncwarp();
        if (pass==0){
            for (int i=lane; i<n; i+=32) atomicAdd(&hist[skey[i]>>24], 1);
        } else {
            int hs = shift + 8;
            for (int i=lane; i<n; i+=32){
                unsigned v = skey[i];
                if ((v>>hs) == prefix) atomicAdd(&hist[(v>>shift)&255u], 1);
            }
        }
        __syncwarp();
        int base = lane*8;
        int h[8]; int tot = 0;
        #pragma unroll
        for (int j=0;j<8;j++){ h[j] = hist[base+j]; tot += h[j]; }
        int run = tot;
        #pragma unroll
        for (int off=1; off<32; off<<=1){
            int t = __shfl_down_sync(0xffffffffu, run, off);
            if (lane + off < 32) run += t;
        }
        int acc = run - tot;
        int cum[8];
        #pragma unroll
        for (int j=7;j>=0;j--){ acc += h[j]; cum[j] = acc; }
        int d_local = -1, cumn_local = 0;
        #pragma unroll
        for (int j=0;j<8;j++){
            if (cum[j] >= kr && cum[j]-h[j] < kr){ d_local = base+j; cumn_local = cum[j]-h[j]; }
        }
        unsigned ball = __ballot_sync(0xffffffffu, d_local >= 0);
        int src = __ffs(ball) - 1;
        int d    = __shfl_sync(0xffffffffu, d_local,    src);
        int cumn = __shfl_sync(0xffffffffu, cumn_local, src);
        kr -= cumn;
        prefix = (prefix<<8) | (unsigned)d;
        __syncwarp();
    }
    T_out = prefix;
    meq_out = kr;
}

__device__ __forceinline__ void warp_compact_bases(
        const unsigned* skey, int n, unsigned T, int m_eq, int lane,
        int& beg, int& end, int& eq_base, int& out_base){
    int ipt = (n + 31)/32;
    beg = lane*ipt; if (beg > n) beg = n;
    end = beg + ipt; if (end > n) end = n;
    int ceq = 0;
    for (int i=beg; i<end; i++) ceq += (skey[i] == T);
    eq_base = warp_excl_scan(ceq, lane);
    int csel = 0;
    { int eqr = eq_base;
      for (int i=beg; i<end; i++){
          unsigned v = skey[i]; int e = (v == T);
          csel += (v > T) || (e && eqr < m_eq);
          eqr += e;
      } }
    out_base = warp_excl_scan(csel, lane);
}

// ---------------- prep kernels ----------------
__global__ void __launch_bounds__(256) prep_rows_kernel(
        const float* __restrict__ src, int srcRowsPerItem, int rowOff, int Lsrc, int Cin,
        fp16* __restrict__ Ph, int RowsAlloc, int K2p, int gran, int Lout){
    int n = blockIdx.y;
    int idx = blockIdx.x*256 + threadIdx.x;
    if (idx >= Lout*gran) return;
    int r = idx / gran, g = idx - r*gran;
    int j0 = g*8, c0 = j0 >> 1;
    int s0 = r - 4, s1 = r - 3;
    float4 fa = {0,0,0,0}, fb = {0,0,0,0};
    if (s0 >= 0 && s0 < Lsrc) fa = *(const float4*)&src[((size_t)n*srcRowsPerItem + rowOff + s0)*Cin + c0];
    if (s1 >= 0 && s1 < Lsrc) fb = *(const float4*)&src[((size_t)n*srcRowsPerItem + rowOff + s1)*Cin + c0];
    float v[8] = {fa.x,fb.x,fa.y,fb.y,fa.z,fb.z,fa.w,fb.w};
    *(uint4*)(Ph + ((size_t)n*RowsAlloc + r)*K2p + j0) = h_pack(v);
}

__global__ void __launch_bounds__(256) prep_docs_kernel(
        const float* __restrict__ pos, const float* __restrict__ neg,
        fp16* __restrict__ Ph){
    const int Lsrc = 479, Cin = 1024, gran = 256, RowsAlloc = 512, K2p = 2048, Lout = 486;
    int n = blockIdx.y;
    int s = n >> 4, b = n & 15;
    const float* src = (s==0) ? (pos + (size_t)b*Lsrc*Cin)
                              : (neg + ((size_t)(s-1)*16 + b)*Lsrc*Cin);
    int idx = blockIdx.x*256 + threadIdx.x;
    if (idx >= Lout*gran) return;
    int r = idx / gran, g = idx - r*gran;
    int j0 = g*8, c0 = j0 >> 1;
    int s0 = r - 4, s1 = r - 3;
    float4 fa = {0,0,0,0}, fb = {0,0,0,0};
    if (s0 >= 0 && s0 < Lsrc) fa = *(const float4*)&src[(size_t)s0*Cin + c0];
    if (s1 >= 0 && s1 < Lsrc) fb = *(const float4*)&src[(size_t)s1*Cin + c0];
    float v[8] = {fa.x,fb.x,fa.y,fb.y,fa.z,fb.z,fa.w,fb.w};
    *(uint4*)(Ph + ((size_t)n*RowsAlloc + r)*K2p + j0) = h_pack(v);
}

__global__ void __launch_bounds__(256) wprep_kernel(
        const float* __restrict__ w, fp16* __restrict__ Wh, int K2, int K2p){
    int gran = K2 >> 3;
    int idx = blockIdx.x*256 + threadIdx.x;
    if (idx >= 300*gran) return;
    int o = idx / gran, g = idx - o*gran;
    int j0 = g*8;
    const float* wr = w + (size_t)o*K2 + j0;
    float4 fa = *(const float4*)wr;
    float4 fb = *(const float4*)(wr+4);
    float v[8] = {fa.x,fa.y,fa.z,fa.w,fb.x,fb.y,fb.z,fb.w};
    *(uint4*)(Wh + (size_t)o*K2p + j0) = h_pack(v);
}

// ---------------- conv1d via mma.sync fp16 (R10 config: 128L x 64O) ---------
#define CPAD 72
#define OFF_A 0
#define OFF_B (128*CPAD*2)
#define CONV_SMEM_SZ (128*65*4)

__global__ void __launch_bounds__(256) conv1d_mma_kernel(
        const fp16* __restrict__ Ph, const fp16* __restrict__ Wh,
        const float* __restrict__ bias, float* __restrict__ outT,
        int RowsAlloc, int K2p, int nch, int Lout){
    extern __shared__ __align__(16) char smem[];
    uint32_t sb = smem_u32(smem);
    int tid = threadIdx.x, wid = tid>>5, lane = tid&31;
    int wm = wid & 3, wn = wid >> 2;
    int l0 = blockIdx.x*128, n0 = blockIdx.y*64, nb = blockIdx.z;
    const fp16* PhN = Ph + (size_t)nb*RowsAlloc*K2p;

    float acc[2][4][4];
    #pragma unroll
    for (int mt=0; mt<2; mt++)
        #pragma unroll
        for (int nt=0; nt<4; nt++)
            #pragma unroll
            for (int e=0; e<4; e++) acc[mt][nt][e] = 0.f;

    int a_row_add = (lane & 7) + ((lane >> 3) & 1)*8;
    int a_col_add = ((lane >> 4) & 1)*8;
    int b_row_add = (lane & 7);
    int b_col_add = ((lane >> 3) & 1)*8;

    for (int ch=0; ch<nch; ch++){
        int jc = ch*64;
        #pragma unroll
        for (int it=0; it<4; it++){
            int task = tid + it*256;
            int r = task >> 3, g = task & 7;
            size_t go = (size_t)(l0 + r)*K2p + jc + g*8;
            *(uint4*)(smem + OFF_A + (uint32_t)(r*CPAD + g*8)*2) = *(const uint4*)(PhN + go);
        }
        #pragma unroll
        for (int it=0; it<2; it++){
            int task = tid + it*256;
            int r = task >> 3, g = task & 7;
            size_t go = (size_t)(n0 + r)*K2p + jc + g*8;
            *(uint4*)(smem + OFF_B + (uint32_t)(r*CPAD + g*8)*2) = *(const uint4*)(Wh + go);
        }
        __syncthreads();
        #pragma unroll
        for (int ks=0; ks<4; ks++){
            uint32_t a_[2][4], b_[4][2];
            #pragma unroll
            for (int mt=0; mt<2; mt++){
                int row = wm*32 + mt*16 + a_row_add;
                ldmx4(a_[mt], sb + OFF_A + (uint32_t)(row*CPAD + ks*16 + a_col_add)*2);
            }
            #pragma unroll
            for (int nt=0; nt<4; nt++){
                int row = wn*32 + nt*8 + b_row_add;
                ldmx2(b_[nt], sb + OFF_B + (uint32_t)(row*CPAD + ks*16 + b_col_add)*2);
            }
            #pragma unroll
            for (int mt=0; mt<2; mt++)
                #pragma unroll
                for (int nt=0; nt<4; nt++)
                    mma_f16(acc[mt][nt], a_[mt], b_[nt]);
        }
        __syncthreads();
    }

    float* sf = (float*)smem;
    int gid = lane >> 2, tig = lane & 3;
    #pragma unroll
    for (int mt=0; mt<2; mt++){
        #pragma unroll
        for (int nt=0; nt<4; nt++){
            int c = wn*32 + nt*8 + tig*2;
            int gcol = n0 + c;
            float b0 = (gcol   < 300) ? __ldg(&bias[gcol])   : 0.f;
            float b1 = (gcol+1 < 300) ? __ldg(&bias[gcol+1]) : 0.f;
            int r0 = wm*32 + mt*16 + gid;
            int r1 = r0 + 8;
            sf[r0*65 + c]   = tanhf(acc[mt][nt][0] + b0);
            sf[r0*65 + c+1] = tanhf(acc[mt][nt][1] + b1);
            sf[r1*65 + c]   = tanhf(acc[mt][nt][2] + b0);
            sf[r1*65 + c+1] = tanhf(acc[mt][nt][3] + b1);
        }
    }
    __syncthreads();
    for (int idx = tid; idx < 64*128; idx += 256){
        int o = idx >> 7, l = idx & 127;
        int go = n0 + o, gl = l0 + l;
        if (go < 300 && gl < Lout)
            outT[((size_t)nb*300 + go)*Lout + gl] = sf[l*65 + o];
    }
}

// ---------------- channel kmax (1024 -> 300): warp per task, 4 warps/block --
__global__ void __launch_bounds__(128) kmax_ch_q_kernel(
        const float* __restrict__ query, float* __restrict__ qg){
    __shared__ unsigned skey[4][1024];
    __shared__ int      hist[4][256];
    int wid = threadIdx.x >> 5, lane = threadIdx.x & 31;
    int l = blockIdx.x*4 + wid, n = blockIdx.y;
    if (l >= 239) return;
    unsigned* sk = skey[wid];
    const float* row = query + ((size_t)n*239 + l)*1024;
    for (int i=lane; i<1024; i+=32) sk[i] = f2u(row[i]);
    __syncwarp();
    unsigned T; int m_eq;
    warp_threshold(sk, 1024, 300, hist[wid], lane, T, m_eq);
    int beg, end, eq_base, out_base;
    warp_compact_bases(sk, 1024, T, m_eq, lane, beg, end, eq_base, out_base);
    float* orow = qg + (size_t)n*480*300 + (size_t)l*300;
    { int eqr = eq_base, p = out_base;
      for (int i=beg; i<end; i++){
          unsigned v = sk[i]; int e = (v == T);
          if ((v > T) || (e && eqr < m_eq)) orow[p++] = u2f(v);
          eqr += e;
      } }
}

__global__ void __launch_bounds__(128) kmax_ch_d_kernel(
        const float* __restrict__ pos, const float* __restrict__ neg,
        float* __restrict__ dg, fp16* __restrict__ dgh){
    __shared__ unsigned skey[4][1024];
    __shared__ int      hist[4][256];
    int wid = threadIdx.x >> 5, lane = threadIdx.x & 31;
    int l = blockIdx.x*4 + wid, n = blockIdx.y;
    if (l >= 479) return;
    int s = n >> 4, b = n & 15;
    const float* row = (s==0) ? (pos + ((size_t)b*479 + l)*1024)
                              : (neg + (((size_t)(s-1)*16 + b)*479 + l)*1024);
    unsigned* sk = skey[wid];
    for (int i=lane; i<1024; i+=32) sk[i] = f2u(row[i]);
    __syncwarp();
    unsigned T; int m_eq;
    warp_threshold(sk, 1024, 300, hist[wid], lane, T, m_eq);
    int beg, end, eq_base, out_base;
    warp_compact_bases(sk, 1024, T, m_eq, lane, beg, end, eq_base, out_base);
    float* orow = dg + (size_t)n*960*300 + (size_t)l*300;
    fp16* prow = dgh + ((size_t)n*960 + l)*320;
    { int eqr = eq_base, p = out_base;
      for (int i=beg; i<end; i++){
          unsigned v = sk[i]; int e = (v == T);
          if ((v > T) || (e && eqr < m_eq)){
              float f = u2f(v);
              orow[p] = f;
              prow[p] = __float2half_rn(f);
              p++;
          }
          eqr += e;
      } }
}

// ---------------- length kmax (transposed input): 4 warps/block -------------
__global__ void __launch_bounds__(128) kmax_len_q_kernel(
        const float* __restrict__ srcT, int Lin, int k,
        float* __restrict__ dstBase){
    __shared__ unsigned skey[4][512];
    __shared__ int      hist[4][256];
    int wid = threadIdx.x >> 5, lane = threadIdx.x & 31;
    int o = blockIdx.x*4 + wid, n = blockIdx.y;
    if (o >= 300) return;
    unsigned* sk = skey[wid];
    const float* row = srcT + ((size_t)n*300 + o)*Lin;
    for (int i=lane; i<Lin; i+=32) sk[i] = f2u(row[i]);
    __syncwarp();
    unsigned T; int m_eq;
    warp_threshold(sk, Lin, k, hist[wid], lane, T, m_eq);
    int beg, end, eq_base, out_base;
    warp_compact_bases(sk, Lin, T, m_eq, lane, beg, end, eq_base, out_base);
    float* dn = dstBase + (size_t)n*480*300;
    { int eqr = eq_base, p = out_base;
      for (int i=beg; i<end; i++){
          unsigned v = sk[i]; int e = (v == T);
          if ((v > T) || (e && eqr < m_eq)) dn[(size_t)(p++)*300 + o] = u2f(v);
          eqr += e;
      } }
}

__global__ void __launch_bounds__(128) kmax_len_d_kernel(
        const float* __restrict__ srcT, int Lin, int k, int rowOff,
        float* __restrict__ dg, fp16* __restrict__ dgh){
    __shared__ unsigned skey[4][512];
    __shared__ int      hist[4][256];
    int wid = threadIdx.x >> 5, lane = threadIdx.x & 31;
    int o = blockIdx.x*4 + wid, n = blockIdx.y;
    if (o >= 300) return;
    unsigned* sk = skey[wid];
    const float* row = srcT + ((size_t)n*300 + o)*Lin;
    for (int i=lane; i<Lin; i+=32) sk[i] = f2u(row[i]);
    __syncwarp();
    unsigned T; int m_eq;
    warp_threshold(sk, Lin, k, hist[wid], lane, T, m_eq);
    int beg, end, eq_base, out_base;
    warp_compact_bases(sk, Lin, T, m_eq, lane, beg, end, eq_base, out_base);
    { int eqr = eq_base, p = out_base;
      for (int i=beg; i<end; i++){
          unsigned v = sk[i]; int e = (v == T);
          if ((v > T) || (e && eqr < m_eq)){
              float f = u2f(v);
              size_t r = (size_t)n*960 + rowOff + p;
              dg[r*300 + o]  = f;
              dgh[r*320 + o] = __float2half_rn(f);
              p++;
          }
          eqr += e;
      } }
}

// ---------------- k=1 max over length ----------------
__global__ void __launch_bounds__(256) maxlen_q_kernel(
        const float* __restrict__ srcT, int Lin, float* __restrict__ dstBase){
    int w = threadIdx.x >> 5, lane = threadIdx.x & 31;
    int o = blockIdx.x*8 + w;
    int n = blockIdx.y;
    if (o >= 300) return;
    const float* row = srcT + ((size_t)n*300 + o)*Lin;
    float m = -FLT_MAX;
    for (int l=lane; l<Lin; l+=32) m = fmaxf(m, row[l]);
    #pragma unroll
    for (int off=16; off; off>>=1)
        m = fmaxf(m, __shfl_down_sync(0xffffffffu, m, off));
    if (lane == 0) dstBase[(size_t)n*480*300 + o] = m;
}

__global__ void __launch_bounds__(256) maxlen_d_kernel(
        const float* __restrict__ srcT, int Lin,
        float* __restrict__ dg, fp16* __restrict__ dgh){
    int w = threadIdx.x >> 5, lane = threadIdx.x & 31;
    int o = blockIdx.x*8 + w;
    int n = blockIdx.y;
    if (o >= 300) return;
    const float* row = srcT + ((size_t)n*300 + o)*Lin;
    float m = -FLT_MAX;
    for (int l=lane; l<Lin; l+=32) m = fmaxf(m, row[l]);
    #pragma unroll
    for (int off=16; off; off>>=1)
        m = fmaxf(m, __shfl_down_sync(0xffffffffu, m, off));
    if (lane == 0){
        size_t r = (size_t)n*960 + 959;
        dg[r*300 + o] = m;
        dgh[r*320 + o] = __float2half_rn(m);
    }
}

// ---------------- SGEMM qt = qg @ bw, fp16 out (pitch 320) ------------------
__global__ void __launch_bounds__(256) sgemm_qt_kernel(
        const float* __restrict__ A, const float* __restrict__ B,
        fp16* __restrict__ qth, int M, int K){
    __shared__ float sA[16][68];
    __shared__ float sB[16][68];
    int tid = threadIdx.x;
    int tx = tid & 15, ty = tid >> 4;
    int n0 = blockIdx.x * 64, m0 = blockIdx.y * 64;
    unsigned long long acc2[4][2];
    #pragma unroll
    for (int i=0;i<4;i++){ acc2[i][0]=0ull; acc2[i][1]=0ull; }
    int row = ty*4, col = tx*4;
    for (int k0 = 0; k0 < K; k0 += 16){
        for (int idx = tid; idx < 1024; idx += BT){
            int kk = idx & 15, m = idx >> 4;
            int gm = m0 + m, gk = k0 + kk;
            sA[kk][m] = (gm < M && gk < K) ? A[(size_t)gm*K + gk] : 0.f;
        }
        for (int idx = tid; idx < 1024; idx += BT){
            int nn = idx & 63, kk = idx >> 6;
            int gn = n0 + nn, gk = k0 + kk;
            sB[kk][nn] = (gn < 300 && gk < K) ? B[(size_t)gk*300 + gn] : 0.f;
        }
        __syncthreads();
        #pragma unroll
        for (int kk=0; kk<16; kk++){
            float4 a4 = *(const float4*)&sA[kk][row];
            ulonglong2 b2 = *(const ulonglong2*)&sB[kk][col];
            unsigned long long d0 = pk2(a4.x,a4.x);
            unsigned long long d1 = pk2(a4.y,a4.y);
            unsigned long long d2 = pk2(a4.z,a4.z);
            unsigned long long d3 = pk2(a4.w,a4.w);
            fma2(acc2[0][0], d0, b2.x); fma2(acc2[0][1], d0, b2.y);
            fma2(acc2[1][0], d1, b2.x); fma2(acc2[1][1], d1, b2.y);
            fma2(acc2[2][0], d2, b2.x); fma2(acc2[2][1], d2, b2.y);
            fma2(acc2[3][0], d3, b2.x); fma2(acc2[3][1], d3, b2.y);
        }
        __syncthreads();
    }
    #pragma unroll
    for (int i=0;i<4;i++){
        int gm = m0 + row + i;
        if (gm >= M) continue;
        #pragma unroll
        for (int j2=0;j2<2;j2++){
            float2 v = upk2(acc2[i][j2]);
            int gn = n0 + col + 2*j2;
            float x0 = (gn   < 300) ? v.x : 0.f;
            float x1 = (gn+1 < 300) ? v.y : 0.f;
            size_t off = (size_t)gm*320 + gn;
            qth[off]   = __float2half_rn(x0);
            qth[off+1] = __float2half_rn(x1);
        }
    }
}

// ---------------- fused match GEMM (mma fp16) + pool + sigmoid --------------
__global__ void __launch_bounds__(256) mpool_mma_kernel(
        const fp16* __restrict__ qth, const fp16* __restrict__ dgh,
        const float* __restrict__ bbp, float* __restrict__ xout){
    __shared__ __align__(16) fp16 sQ[96*40];
    __shared__ __align__(16) fp16 sD[96*40];
    __shared__ unsigned pool[32];
    int tid = threadIdx.x, wid = tid>>5, lane = tid&31;
    int wm = wid & 1, wn = wid >> 1;
    int n = blockIdx.z, b = n & 15;
    int q0 = blockIdx.y*96, d0 = blockIdx.x*96;
    const fp16* Q = qth + ((size_t)b*480 + q0)*320;
    const fp16* D = dgh + ((size_t)n*960 + d0)*320;

    float acc[3][3][4];
    #pragma unroll
    for (int mt=0; mt<3; mt++)
        #pragma unroll
        for (int nt=0; nt<3; nt++)
            #pragma unroll
            for (int e=0; e<4; e++) acc[mt][nt][e] = 0.f;

    int a_row_add = (lane & 7) + ((lane >> 3) & 1)*8;
    int a_col_add = ((lane >> 4) & 1)*8;
    int b_row_add = (lane & 7);
    int b_col_add = ((lane >> 3) & 1)*8;
    uint32_t sQ_b = smem_u32(sQ), sD_b = smem_u32(sD);

    for (int ch=0; ch<10; ch++){
        int k0 = ch*32;
        #pragma unroll
        for (int it=0; it<3; it++){
            int t = tid + it*256;
            int plane = t / 384, rem = t - plane*384;
            int r = rem >> 2, g = rem & 3;
            const fp16* gsrc = plane ? D : Q;
            fp16* sdst = plane ? sD : sQ;
            uint4 v = *(const uint4*)(gsrc + (size_t)r*320 + k0 + g*8);
            *(uint4*)(sdst + r*40 + g*8) = v;
        }
        __syncthreads();
        #pragma unroll
        for (int ks=0; ks<2; ks++){
            uint32_t q_[3][4], d_[3][2];
            #pragma unroll
            for (int mt=0; mt<3; mt++){
                int row = wm*48 + mt*16 + a_row_add;
                ldmx4(q_[mt], sQ_b + (uint32_t)(row*40 + ks*16 + a_col_add)*2);
            }
            #pragma unroll
            for (int nt=0; nt<3; nt++){
                int row = wn*24 + nt*8 + b_row_add;
                ldmx2(d_[nt], sD_b + (uint32_t)(row*40 + ks*16 + b_col_add)*2);
            }
            #pragma unroll
            for (int mt=0; mt<3; mt++)
                #pragma unroll
                for (int nt=0; nt<3; nt++)
                    mma_f16(acc[mt][nt], q_[mt], d_[nt]);
        }
        __syncthreads();
    }

    if (tid < 32) pool[tid] = 0u;
    __syncthreads();
    int gid = lane >> 2;
    #pragma unroll
    for (int mt=0; mt<3; mt++){
        float m0 = -FLT_MAX, m1 = -FLT_MAX;
        #pragma unroll
        for (int nt=0; nt<3; nt++){
            m0 = fmaxf(m0, fmaxf(acc[mt][nt][0], acc[mt][nt][1]));
            m1 = fmaxf(m1, fmaxf(acc[mt][nt][2], acc[mt][nt][3]));
        }
        int r0 = wm*48 + mt*16 + gid;
        int r1 = r0 + 8;
        atomicMax(&pool[(r0/12)*4 + wn], f2u(m0));
        atomicMax(&pool[(r1/12)*4 + wn], f2u(m1));
    }
    __syncthreads();
    if (tid < 32){
        int qc = tid >> 2, dc = tid & 3;
        float logit = u2f(pool[tid]) + bbp[0];
        int gi = blockIdx.y*8 + qc, gj = blockIdx.x*4 + dc;
        xout[((size_t)n*40 + gi)*40 + gj] = sigm(logit);
    }
}

// ---------------- 2D conv tower block ----------------
__global__ void __launch_bounds__(256) convtower_kernel(
        const float* __restrict__ xin, const float* __restrict__ mw,
        const float* __restrict__ mb, float* __restrict__ xout){
    __shared__ float sx[40][40];
    __shared__ float swt[50][4];
    __shared__ float sb[50];
    int n = blockIdx.x, tid = threadIdx.x;
    for (int idx=tid; idx<1600; idx+=blockDim.x)
        sx[idx/40][idx%40] = xin[(size_t)n*1600 + idx];
    for (int idx=tid; idx<200; idx+=blockDim.x)
        swt[idx>>2][idx&3] = mw[idx];
    for (int idx=tid; idx<50; idx+=blockDim.x)
        sb[idx] = mb[idx];
    __syncthreads();
    for (int cell=tid; cell<1600; cell+=blockDim.x){
        int i = cell/40, j = cell%40;
        int hs = (i*47)/40,  he = ((i+1)*47 + 39)/40;
        int ws = (j*47)/40,  we = ((j+1)*47 + 39)/40;
        float m = -FLT_MAX;
        for (int h=hs; h<he; h++)
            for (int w=ws; w<we; w++){
                int r0=h-4, r1=h-3, c0=w-4, c1=w-3;
                float x00 = (r0>=0 && r0<40 && c0>=0 && c0<40) ? sx[r0][c0] : 0.f;
                float x01 = (r0>=0 && r0<40 && c1>=0 && c1<40) ? sx[r0][c1] : 0.f;
                float x10 = (r1>=0 && r1<40 && c0>=0 && c0<40) ? sx[r1][c0] : 0.f;
                float x11 = (r1>=0 && r1<40 && c1>=0 && c1<40) ? sx[r1][c1] : 0.f;
                for (int o=0;o<50;o++){
                    float l = fmaf(x00, swt[o][0],
                              fmaf(x01, swt[o][1],
                              fmaf(x10, swt[o][2],
                              fmaf(x11, swt[o][3], sb[o]))));
                    m = fmaxf(m, l);
                }
            }
        xout[(size_t)n*1600 + cell] = sigm(m);
    }
}

// ---------------- final logistic head ----------------
__global__ void __launch_bounds__(64) final_kernel(
        const float* __restrict__ feat, const float* __restrict__ lw,
        const float* __restrict__ lb, float* __restrict__ out){
    __shared__ float sh[40];
    int n = blockIdx.x, tid = threadIdx.x;
    if (tid < 40){
        float a = 0.f;
        const float* f = feat + (size_t)n*1600 + tid*40;
        for (int j=0;j<40;j++) a += f[j]*lw[j];
        sh[tid] = sigm(a + lb[0]);
    }
    __syncthreads();
    if (tid == 0){
        float a = 0.f;
        for (int i=0;i<40;i++) a += sh[i]*lw[i];
        out[n] = sigm(a + lb[0]);
    }
}

// ---------------- launch ----------------
extern "C" void kernel_launch(void* const* d_in, const int* in_sizes, int n_in,
                              void* d_out, int out_size){
    const float* query = (const float*)d_in[0];
    const float* pos   = (const float*)d_in[1];
    const float* neg   = (const float*)d_in[2];
    const float* qw1 = (const float*)d_in[3];  const float* qb1 = (const float*)d_in[4];
    const float* qw2 = (const float*)d_in[5];  const float* qb2 = (const float*)d_in[6];
    const float* qw3 = (const float*)d_in[7];  const float* qb3 = (const float*)d_in[8];
    const float* dw1 = (const float*)d_in[9];  const float* db1 = (const float*)d_in[10];
    const float* dw2 = (const float*)d_in[11]; const float* db2 = (const float*)d_in[12];
    const float* dw3 = (const float*)d_in[13]; const float* db3 = (const float*)d_in[14];
    const float* bw  = (const float*)d_in[15]; const float* bb  = (const float*)d_in[16];
    const float* mw1 = (const float*)d_in[17]; const float* mb1 = (const float*)d_in[18];
    const float* mw2 = (const float*)d_in[19]; const float* mb2 = (const float*)d_in[20];
    const float* mw3 = (const float*)d_in[21]; const float* mb3 = (const float*)d_in[22];
    const float* lw  = (const float*)d_in[23]; const float* lb  = (const float*)d_in[24];
    float* out = (float*)d_out;

    float *qc1, *qc2, *qc3, *qg, *dc1, *dc2, *dc3, *dg, *x0, *x1;
    fp16 *qtb, *dgb, *qP1, *qP2, *qP3, *dP1, *dP2, *dP3;
    fp16 *wq1, *wq2, *wq3, *wd1, *wd2, *wd3;
    cudaGetSymbolAddress((void**)&qc1,  g_qc1);
    cudaGetSymbolAddress((void**)&qc2,  g_qc2);
    cudaGetSymbolAddress((void**)&qc3,  g_qc3);
    cudaGetSymbolAddress((void**)&qg,   g_qg);
    cudaGetSymbolAddress((void**)&dc1,  g_dc1);
    cudaGetSymbolAddress((void**)&dc2,  g_dc2);
    cudaGetSymbolAddress((void**)&dc3,  g_dc3);
    cudaGetSymbolAddress((void**)&dg,   g_dg);
    cudaGetSymbolAddress((void**)&x0,   g_x0);
    cudaGetSymbolAddress((void**)&x1,   g_x1);
    cudaGetSymbolAddress((void**)&qtb,  g_qtb);
    cudaGetSymbolAddress((void**)&dgb,  g_dgb);
    cudaGetSymbolAddress((void**)&qP1,  g_qP1);
    cudaGetSymbolAddress((void**)&qP2,  g_qP2);
    cudaGetSymbolAddress((void**)&qP3,  g_qP3);
    cudaGetSymbolAddress((void**)&dP1,  g_dP1);
    cudaGetSymbolAddress((void**)&dP2,  g_dP2);
    cudaGetSymbolAddress((void**)&dP3,  g_dP3);
    cudaGetSymbolAddress((void**)&wq1,  g_wq1);
    cudaGetSymbolAddress((void**)&wq2,  g_wq2);
    cudaGetSymbolAddress((void**)&wq3,  g_wq3);
    cudaGetSymbolAddress((void**)&wd1,  g_wd1);
    cudaGetSymbolAddress((void**)&wd2,  g_wd2);
    cudaGetSymbolAddress((void**)&wd3,  g_wd3);

    cudaFuncSetAttribute(conv1d_mma_kernel,
                         cudaFuncAttributeMaxDynamicSharedMemorySize, CONV_SMEM_SZ);

    wprep_kernel<<<300, 256>>>(dw1, wd1, 2048, 2048);
    prep_docs_kernel<<<dim3(486, 80), 256>>>(pos, neg, dP1);
    kmax_ch_q_kernel<<<dim3(60, 16), 128>>>(query, qg);
    kmax_ch_d_kernel<<<dim3(120, 80), 128>>>(pos, neg, dg, dgb);
    wprep_kernel<<<300, 256>>>(qw1, wq1, 2048, 2048);
    conv1d_mma_kernel<<<dim3(4,5,80), 256, CONV_SMEM_SZ>>>(dP1, wd1, db1, dc1, 512, 2048, 32, 486);
    kmax_len_d_kernel<<<dim3(75,80), 128>>>(dc1, 486, 320, 479, dg, dgb);

    wprep_kernel<<<88, 256>>>(qw2, wq2, 600, 640);
    wprep_kernel<<<88, 256>>>(qw3, wq3, 600, 640);
    wprep_kernel<<<88, 256>>>(dw2, wd2, 600, 640);
    wprep_kernel<<<88, 256>>>(dw3, wd3, 600, 640);

    // ===== query tower =====
    prep_rows_kernel<<<dim3(246, 16), 256>>>(query, 239, 0, 239, 1024, qP1, 256, 2048, 256, 246);
    conv1d_mma_kernel<<<dim3(2,5,16), 256, CONV_SMEM_SZ>>>(qP1, wq1, qb1, qc1, 256, 2048, 32, 246);
    kmax_len_q_kernel<<<dim3(75,16), 128>>>(qc1, 246, 160, qg + 239*300);
    prep_rows_kernel<<<dim3(49, 16), 256>>>(qg, 480, 239, 160, 300, qP2, 256, 640, 75, 167);
    conv1d_mma_kernel<<<dim3(2,5,16), 256, CONV_SMEM_SZ>>>(qP2, wq2, qb2, qc2, 256, 640, 10, 167);
    kmax_len_q_kernel<<<dim3(75,16), 128>>>(qc2, 167, 80, qg + 399*300);
    prep_rows_kernel<<<dim3(26, 16), 256>>>(qg, 480, 399, 80, 300, qP3, 128, 640, 75, 87);
    conv1d_mma_kernel<<<dim3(1,5,16), 256, CONV_SMEM_SZ>>>(qP3, wq3, qb3, qc3, 128, 640, 10, 87);
    maxlen_q_kernel<<<dim3(38,16), 256>>>(qc3, 87, qg + 479*300);

    // ===== doc tower (cont.) =====
    prep_rows_kernel<<<dim3(96, 80), 256>>>(dg, 960, 479, 320, 300, dP2, 384, 640, 75, 327);
    conv1d_mma_kernel<<<dim3(3,5,80), 256, CONV_SMEM_SZ>>>(dP2, wd2, db2, dc2, 384, 640, 10, 327);
    kmax_len_d_kernel<<<dim3(75,80), 128>>>(dc2, 327, 160, 799, dg, dgb);
    prep_rows_kernel<<<dim3(49, 80), 256>>>(dg, 960, 799, 160, 300, dP3, 256, 640, 75, 167);
    conv1d_mma_kernel<<<dim3(2,5,80), 256, CONV_SMEM_SZ>>>(dP3, wd3, db3, dc3, 256, 640, 10, 167);
    maxlen_d_kernel<<<dim3(38,80), 256>>>(dc3, 167, dg, dgb);

    // ===== bilinear + fused match/pool =====
    sgemm_qt_kernel<<<dim3(5, 120), 256>>>(qg, bw, qtb, 16*480, 300);
    mpool_mma_kernel<<<dim3(10, 5, 80), 256>>>(qtb, dgb, bb, x0);

    convtower_kernel<<<80, 256>>>(x0, mw1, mb1, x1);
    convtower_kernel<<<80, 256>>>(x1, mw2, mb2, x0);
    convtower_kernel<<<80, 256>>>(x0, mw3, mb3, x1);

    final_kernel<<<80, 64>>>(x1, lw, lb, out);
}